// round 1
// baseline (speedup 1.0000x reference)
#include <cuda_runtime.h>
#include <cuda_bf16.h>

// Fused: conv2d 3x3 SAME (NCHW, OIHW) -> min over C_out -> * 2.0
// x: (32, 64, 128, 128) f32, W: (128, 64, 3, 3) f32, out: (32, 1, 128, 128) f32
//
// Strategy (round 1 baseline, fp32 FFMA):
//  - grid: (tiles_x=2, tiles_y=8, batch=32) = 512 blocks, 128 threads
//  - block tile: 16 rows x 64 cols of output pixels; thread = 1 row x 8 cols
//  - oc processed in 16 chunks of 8; per chunk each thread keeps acc[8][8] regs
//  - per (occ, ic): x tile (18 x 66, zero-padded) staged in smem, W chunk
//    (8 oc x 576) staged in smem once per occ
//  - min-reduce the 8 oc accs into minv[8] after each chunk, write minv*2 at end

#define TILE_H 16
#define TILE_W 64
#define TPB    128
#define SX_COLS 68   // 66 used, padded stride

__global__ void __launch_bounds__(TPB, 4)
conv_min_scale_kernel(const float* __restrict__ x,
                      const float* __restrict__ Wt,
                      float* __restrict__ out)
{
    const int b   = blockIdx.z;
    const int ty0 = blockIdx.y * TILE_H;
    const int tx0 = blockIdx.x * TILE_W;
    const int tid = threadIdx.x;
    const int ty  = tid >> 3;          // 0..15
    const int tx  = (tid & 7) << 3;    // 0,8,...,56

    __shared__ float sX[TILE_H + 2][SX_COLS];  // 18 x 68
    __shared__ float sW[8][576];               // 8 oc * (64 ic * 9)

    float minv[8];
#pragma unroll
    for (int p = 0; p < 8; ++p) minv[p] = 3.4028235e38f;

    const float* xb = x + (long long)b * 64 * 128 * 128;

    for (int occ = 0; occ < 16; ++occ) {
        // protect sW/sX from readers of previous chunk
        __syncthreads();
        // stage 8 output channels of weights: 4608 floats
#pragma unroll
        for (int i = tid; i < 8 * 576; i += TPB) {
            int oc = i / 576;
            int r  = i - oc * 576;
            sW[oc][r] = Wt[(occ * 8 + oc) * 576 + r];
        }

        float acc[8][8];
#pragma unroll
        for (int o = 0; o < 8; ++o)
#pragma unroll
            for (int p = 0; p < 8; ++p) acc[o][p] = 0.0f;

        for (int ic = 0; ic < 64; ++ic) {
            __syncthreads();   // previous compute done reading sX
            const float* xc = xb + ic * 128 * 128;
            // stage 18 x 66 input tile (zero pad at borders)
            for (int i = tid; i < 18 * 66; i += TPB) {
                int r = i / 66;
                int c = i - r * 66;
                int gy = ty0 - 1 + r;
                int gx = tx0 - 1 + c;
                float v = 0.0f;
                if ((unsigned)gy < 128u && (unsigned)gx < 128u)
                    v = xc[gy * 128 + gx];
                sX[r][c] = v;
            }
            __syncthreads();

#pragma unroll
            for (int ky = 0; ky < 3; ++ky) {
                float xr[10];
#pragma unroll
                for (int j = 0; j < 10; ++j)
                    xr[j] = sX[ty + ky][tx + j];

                const int wbase = ic * 9 + ky * 3;
#pragma unroll
                for (int o = 0; o < 8; ++o) {
                    const float w0 = sW[o][wbase + 0];
                    const float w1 = sW[o][wbase + 1];
                    const float w2 = sW[o][wbase + 2];
#pragma unroll
                    for (int p = 0; p < 8; ++p) {
                        acc[o][p] = fmaf(xr[p + 0], w0, acc[o][p]);
                        acc[o][p] = fmaf(xr[p + 1], w1, acc[o][p]);
                        acc[o][p] = fmaf(xr[p + 2], w2, acc[o][p]);
                    }
                }
            }
        }

#pragma unroll
        for (int o = 0; o < 8; ++o)
#pragma unroll
            for (int p = 0; p < 8; ++p)
                minv[p] = fminf(minv[p], acc[o][p]);
    }

    float* ob = out + (long long)b * 128 * 128;
    const int gy = ty0 + ty;
    const int gx = tx0 + tx;
#pragma unroll
    for (int p = 0; p < 8; ++p)
        ob[gy * 128 + gx + p] = minv[p] * 2.0f;
}

extern "C" void kernel_launch(void* const* d_in, const int* in_sizes, int n_in,
                              void* d_out, int out_size)
{
    const float* x  = (const float*)d_in[0];  // (32,64,128,128)
    const float* Wt = (const float*)d_in[1];  // (128,64,3,3)
    float* out = (float*)d_out;               // (32,1,128,128)

    dim3 grid(128 / TILE_W, 128 / TILE_H, 32); // (2, 8, 32)
    dim3 block(TPB);
    conv_min_scale_kernel<<<grid, block>>>(x, Wt, out);
}